// round 12
// baseline (speedup 1.0000x reference)
#include <cuda_runtime.h>
#include <cuda_fp16.h>
#include <mma.h>
using namespace nvcuda;

#define NB 4
#define NC 64
#define NN 8192
#define NK 16
#define NO 64
#define EPSV 1e-5f

// Combined y, fp16: [b][n][128] halves. ch 0-63  = y1 = inv*(W1-W2)@x  (gather via e1)
//                                      ch 64-127 = y2 = inv*W2@x + shift (gather via e0)
__device__ __align__(16) __half g_y[(size_t)NB * NN * 128];

#define XH_LD 136   // sXh [c][n] fp16 (128 + 8 pad)
#define WH_LD 136   // sWh [c][o] fp16 (128 + 8 pad)
#define ST_LD 72    // epilogue staging row stride (floats)

#define SMEM_XH 0                 // 64*136*2 = 17408
#define SMEM_WH 17408             // 64*136*2 = 17408
#define SMEM_SH 36864             // 128 floats = 512 (after staging region)
#define SMEM_TOT 37376
// Epilogue staging reuses [0, 36864): 8 warps x 16 rows x 72 floats.

// ---------------------------------------------------------------------------
// Kernel A (tensor cores): 128-node x 128-out block (R10 skeleton).
// 8 warps; warp = 16 nodes x 128 outs (8 wmma tiles), 4 k-steps.
// Fixes vs R10: (1) epilogue restaged so each STG.128 covers 4 FULL 128B
// lines (was 16 partial lines); (2) BN inv folded inline (no sinv smem, one
// fewer __syncthreads); (3) 8B-packed STS in staging.
// ---------------------------------------------------------------------------
__global__ __launch_bounds__(256, 2) void kA(
    const float* __restrict__ x, const float* __restrict__ W,
    const float* __restrict__ gamma, const float* __restrict__ beta,
    const float* __restrict__ rmean, const float* __restrict__ rvar)
{
    __shared__ __align__(16) char smem[SMEM_TOT];
    __half* sXh    = (__half*)(smem + SMEM_XH);
    __half* sWh    = (__half*)(smem + SMEM_WH);
    float*  sshift = (float*)(smem + SMEM_SH);

    const int tid  = threadIdx.x;
    const int b    = blockIdx.y;
    const int n0b  = blockIdx.x * 128;
    const int w    = tid >> 5;
    const int lane = tid & 31;

    // BN shift (outs 64..127 only; 0 for y1 half).
    if (tid < 128) {
        float s = 0.f;
        if (tid >= 64) {
            int o2 = tid - 64;
            s = beta[o2] - rmean[o2] * gamma[o2] * rsqrtf(rvar[o2] + EPSV);
        }
        sshift[tid] = s;
    }

    // Stage X tile: [64 c][128 n] fp32 -> fp16, coalesced float4 reads, 8B STS.
    {
        const float4* xp = (const float4*)(x + (size_t)b * NC * NN + n0b);
        for (int i = tid; i < 64 * 32; i += 256) {
            int c = i >> 5, j = i & 31;
            float4 v = xp[(size_t)c * (NN / 4) + j];
            uint2 u;
            ((__half2*)&u)[0] = __floats2half2_rn(v.x, v.y);
            ((__half2*)&u)[1] = __floats2half2_rn(v.z, v.w);
            *(uint2*)&sXh[c * XH_LD + 4 * j] = u;
        }
    }

    // Stage folded W: sWh[c][o]; o<64 -> (W1-W2)*inv, o>=64 -> W2*inv.
    // BN inv computed inline (broadcast gamma/rvar loads, cached).
    for (int i = tid; i < 2048; i += 256) {
        int q = i >> 6, c = i & 63;
        int o0 = q * 4;
        float v[4];
#pragma unroll
        for (int j = 0; j < 4; j++) {
            int o = o0 + j;
            if (o < 64) {
                float inv = gamma[o] * rsqrtf(rvar[o] + EPSV);
                v[j] = (W[o * 128 + c] - W[o * 128 + 64 + c]) * inv;
            } else {
                int o2 = o - 64;
                float inv = gamma[o2] * rsqrtf(rvar[o2] + EPSV);
                v[j] = W[o2 * 128 + 64 + c] * inv;
            }
        }
        uint2 u;
        ((__half2*)&u)[0] = __floats2half2_rn(v[0], v[1]);
        ((__half2*)&u)[1] = __floats2half2_rn(v[2], v[3]);
        *(uint2*)&sWh[c * WH_LD + o0] = u;
    }
    __syncthreads();

    // Mainloop: warp covers nodes [w*16, +16), all 128 outs.
    const int n0 = w * 16;
    wmma::fragment<wmma::matrix_a, 16, 16, 16, __half, wmma::col_major> af;
    wmma::fragment<wmma::matrix_b, 16, 16, 16, __half, wmma::row_major> bf;
    wmma::fragment<wmma::accumulator, 16, 16, 16, float> acc[8];
#pragma unroll
    for (int t = 0; t < 8; t++) wmma::fill_fragment(acc[t], 0.0f);

#pragma unroll
    for (int k = 0; k < 4; k++) {
        wmma::load_matrix_sync(af, sXh + k * 16 * XH_LD + n0, XH_LD);
#pragma unroll
        for (int t = 0; t < 8; t++) {
            wmma::load_matrix_sync(bf, sWh + k * 16 * WH_LD + t * 16, WH_LD);
            wmma::mma_sync(acc[t], af, bf, acc[t]);
        }
    }
    __syncthreads();   // smem reused for epilogue staging

    // Epilogue: two 64-out halves. Stage warp's 16n x 64o to smem, re-read so
    // lanes 0-7 cover one node's contiguous 128B half-row -> each STG.128
    // covers 4 full 128B lines.
    float* st = (float*)smem + w * (16 * ST_LD);
    const int nl_base = lane >> 3;   // node sub-index 0..3
    const int sl      = lane & 7;    // 8-out (16B) slice
#pragma unroll
    for (int ho = 0; ho < 2; ho++) {
#pragma unroll
        for (int j = 0; j < 4; j++)
            wmma::store_matrix_sync(st + 16 * j, acc[4 * ho + j], ST_LD,
                                    wmma::mem_row_major);
        __syncwarp();
        int ob = ho * 64 + sl * 8;
        float4 s0 = *(const float4*)(sshift + ob);
        float4 s1 = *(const float4*)(sshift + ob + 4);
#pragma unroll
        for (int p = 0; p < 4; p++) {
            int nl = p * 4 + nl_base;
            const float* row = st + nl * ST_LD + sl * 8;
            float4 f0 = *(const float4*)(row);
            float4 f1 = *(const float4*)(row + 4);
            __half2 hh[4];
            hh[0] = __floats2half2_rn(f0.x + s0.x, f0.y + s0.y);
            hh[1] = __floats2half2_rn(f0.z + s0.z, f0.w + s0.w);
            hh[2] = __floats2half2_rn(f1.x + s1.x, f1.y + s1.y);
            hh[3] = __floats2half2_rn(f1.z + s1.z, f1.w + s1.w);
            int n = n0b + n0 + nl;
            *(uint4*)(&g_y[(((size_t)b * NN + n) << 7) + ob]) = *(uint4*)hh;
        }
        __syncwarp();
    }
}

// ---------------------------------------------------------------------------
// Kernel B: edge gather + leaky + max, fp16 y, wide gathers (R10 exact).
// ---------------------------------------------------------------------------
__global__ __launch_bounds__(256) void kB(
    const int* __restrict__ ei, float* __restrict__ out)
{
    __shared__ int  sIdx[1024];      // [0:512) e0 rows, [512:1024) e1 rows
    __shared__ float sm[64 * 33];

    const int tid  = threadIdx.x;
    const int w    = tid >> 5;
    const int lane = tid & 31;
    const int b    = blockIdx.y;
    const int n0   = blockIdx.x * 32;

    const int* e0 = ei + (size_t)b * NN * NK + (size_t)n0 * NK;
    const int* e1 = e0 + (size_t)NB * NN * NK;

    if (tid < 128) ((int4*)sIdx)[tid] = ((const int4*)e0)[tid];
    else           ((int4*)sIdx)[tid] = ((const int4*)e1)[tid - 128];
    __syncthreads();

    const char* yb = (const char*)g_y + ((size_t)b * NN * 256);
    const __half2 NEGI  = __half2half2(__ushort_as_half(0xFC00));
    const __half2 SLOPE = __float2half2_rn(0.2f);

    const int nl  = w * 4 + (lane >> 3);
    const int sub = lane & 7;
    const int* i0p = &sIdx[nl * NK];
    const int* i1p = &sIdx[512 + nl * NK];

    __half2 m[4] = {NEGI, NEGI, NEGI, NEGI};
#pragma unroll
    for (int k = 0; k < 16; k++) {
        int i0 = i0p[k];
        int i1 = i1p[k];
        uint4 av = *(const uint4*)(yb + (i1 << 8) + (sub << 4));        // y1
        uint4 cv = *(const uint4*)(yb + (i0 << 8) + 128 + (sub << 4));  // y2
        const __half2* a = (const __half2*)&av;
        const __half2* c = (const __half2*)&cv;
#pragma unroll
        for (int q = 0; q < 4; q++) {
            __half2 hq = __hadd2(a[q], c[q]);
            hq = __hmax2(hq, __hmul2(hq, SLOPE));
            m[q] = __hmax2(m[q], hq);
        }
    }
#pragma unroll
    for (int q = 0; q < 4; q++) {
        float2 f = __half22float2(m[q]);
        sm[(sub * 8 + 2 * q)     * 33 + nl] = f.x;
        sm[(sub * 8 + 2 * q + 1) * 33 + nl] = f.y;
    }
    __syncthreads();

#pragma unroll
    for (int i = 0; i < 8; i++) {
        int o = i * 8 + w;
        out[((size_t)(b * NO + o)) * NN + n0 + lane] = sm[o * 33 + lane];
    }
}

extern "C" void kernel_launch(void* const* d_in, const int* in_sizes, int n_in,
                              void* d_out, int out_size)
{
    const float* x     = (const float*)d_in[0];
    const int*   ei    = (const int*)d_in[1];
    const float* W     = (const float*)d_in[2];
    const float* gamma = (const float*)d_in[3];
    const float* beta  = (const float*)d_in[4];
    const float* rmean = (const float*)d_in[5];
    const float* rvar  = (const float*)d_in[6];
    float*       out   = (float*)d_out;

    kA<<<dim3(NN / 128, NB), 256>>>(x, W, gamma, beta, rmean, rvar);
    kB<<<dim3(NN / 32, NB), 256>>>(ei, out);
}